// round 8
// baseline (speedup 1.0000x reference)
#include <cuda_runtime.h>
#include <cstdint>
#include <cstddef>

#define TT_T 256      // tokens
#define HH 1024       // hidden
#define EE 256        // experts
#define II 256        // intermediate
#define NPAIR 2048    // T * top_k

typedef unsigned long long u64;

// ---------------- scratch (device globals; no allocations allowed) ----------------
__device__ float g_scores[TT_T * EE];
__device__ int   g_cnt[EE];
__device__ int   g_base[EE];
__device__ int   g_pair_tok[NPAIR];
__device__ float g_pair_w[NPAIR];
// partial sums (per h-half) for routed experts and shared expert
__device__ float g_p1[2][NPAIR * II];
__device__ float g_p3[2][NPAIR * II];
__device__ float g_sp1[2][TT_T * II];
__device__ float g_sp3[2][TT_T * II];

// ---------------- f32x2 / async helpers ----------------
__device__ __forceinline__ u64 fma2(u64 a, u64 b, u64 c) {
    u64 d;
    asm("fma.rn.f32x2 %0, %1, %2, %3;" : "=l"(d) : "l"(a), "l"(b), "l"(c));
    return d;
}
__device__ __forceinline__ u64 pack2(float x, float y) {
    u64 r;
    asm("mov.b64 %0, {%1, %2};" : "=l"(r) : "f"(x), "f"(y));
    return r;
}
__device__ __forceinline__ float2 unpack2(u64 v) {
    float2 r;
    asm("mov.b64 {%0, %1}, %2;" : "=f"(r.x), "=f"(r.y) : "l"(v));
    return r;
}
__device__ __forceinline__ unsigned smem_u32(const void* p) {
    return (unsigned)__cvta_generic_to_shared(p);
}
__device__ __forceinline__ void cp16(unsigned dst, const void* src) {
    asm volatile("cp.async.cg.shared.global [%0], [%1], 16;\n" :: "r"(dst), "l"(src));
}
__device__ __forceinline__ void cp_commit() { asm volatile("cp.async.commit_group;\n"); }
template <int N>
__device__ __forceinline__ void cp_wait() { asm volatile("cp.async.wait_group %0;\n" :: "n"(N)); }
__device__ __forceinline__ float silu_mul(float g, float u) {
    return g / (1.f + __expf(-g)) * u;
}

// ---------------- kernel: zero output ----------------
__global__ void k_zero(float* __restrict__ out, int n) {
    int i = blockIdx.x * blockDim.x + threadIdx.x;
    if (i < n) out[i] = 0.f;
}

// ---------------- kernel: gate scores = sigmoid(x @ gate_w^T) ----------------
__global__ void k_gate(const float* __restrict__ x, const float* __restrict__ gw) {
    __shared__ float gws[8 * HH];
    int eg = blockIdx.x & 31;
    int tg = blockIdx.x >> 5;
    int tid = threadIdx.x;
    for (int idx = tid; idx < 8 * HH; idx += 256)
        gws[idx] = gw[eg * 8 * HH + idx];
    __syncthreads();
    int warp = tid >> 5, lane = tid & 31;
    for (int tt = warp; tt < 32; tt += 8) {
        int t = tg * 32 + tt;
        float acc[8];
#pragma unroll
        for (int e = 0; e < 8; e++) acc[e] = 0.f;
        for (int h = lane; h < HH; h += 32) {
            float xv = x[t * HH + h];
#pragma unroll
            for (int e = 0; e < 8; e++) acc[e] += xv * gws[e * HH + h];
        }
#pragma unroll
        for (int e = 0; e < 8; e++) {
            float v = acc[e];
#pragma unroll
            for (int s = 16; s > 0; s >>= 1) v += __shfl_xor_sync(0xffffffffu, v, s);
            if (lane == e)
                g_scores[t * EE + eg * 8 + e] = 1.f / (1.f + __expf(-v));
        }
    }
}

// ---------------- kernel: routing (1 block, thread = token) ----------------
__global__ void k_route(const float* __restrict__ e_bias) {
    int t = threadIdx.x;
    __shared__ float s_bias[EE];
    __shared__ int s_cnt[EE];
    __shared__ int s_ofs[EE];
    s_bias[t] = e_bias[t];
    s_cnt[t] = 0;
    __syncthreads();
    const float* srow = g_scores + t * EE;

    float gsum[8];
#pragma unroll
    for (int g = 0; g < 8; g++) {
        float m1 = -1e30f, m2 = -1e30f;
        for (int j = 0; j < 32; j++) {
            float v = srow[g * 32 + j] + s_bias[g * 32 + j];
            if (v > m1) { m2 = m1; m1 = v; }
            else if (v > m2) { m2 = v; }
        }
        gsum[g] = m1 + m2;
    }
    unsigned gmask = 0;
    for (int it = 0; it < 4; it++) {
        float best = -1e30f; int bi = 0;
#pragma unroll
        for (int g = 0; g < 8; g++)
            if (!((gmask >> g) & 1u) && gsum[g] > best) { best = gsum[g]; bi = g; }
        gmask |= 1u << bi;
    }
    float bv[8]; int bidx[8];
#pragma unroll
    for (int k = 0; k < 8; k++) { bv[k] = -1e30f; bidx[k] = -1; }
    for (int g = 0; g < 8; g++) {
        if (!((gmask >> g) & 1u)) continue;
        for (int j = 0; j < 32; j++) {
            int e = g * 32 + j;
            float v = srow[e] + s_bias[e];
            if (v > bv[7]) {
#pragma unroll
                for (int k = 7; k > 0; k--) {
                    bool sh = v > bv[k - 1];
                    bool ins = (v > bv[k]) && !sh;
                    float nv = sh ? bv[k - 1] : (ins ? v : bv[k]);
                    int   ni = sh ? bidx[k - 1] : (ins ? e : bidx[k]);
                    bv[k] = nv; bidx[k] = ni;
                }
                if (v > bv[0]) { bv[0] = v; bidx[0] = e; }
            }
        }
    }
    float w[8]; float wsum = 0.f;
#pragma unroll
    for (int k = 0; k < 8; k++) { w[k] = srow[bidx[k]]; wsum += w[k]; }
    float scl = 2.5f / (wsum + 1e-20f);
#pragma unroll
    for (int k = 0; k < 8; k++) {
        w[k] *= scl;
        atomicAdd(&s_cnt[bidx[k]], 1);
    }
    __syncthreads();
    int base = 0;
    for (int e = 0; e < t; e++) base += s_cnt[e];
    s_ofs[t] = base;
    g_base[t] = base;
    g_cnt[t] = s_cnt[t];
    __syncthreads();
#pragma unroll
    for (int k = 0; k < 8; k++) {
        int slot = atomicAdd(&s_ofs[bidx[k]], 1);
        g_pair_tok[slot] = t;
        g_pair_w[slot] = w[k];
    }
}

// ================= mlp1: token-pair x col-pair blocking, h-half split =================
// 128 threads; thread owns cols (2*tid, 2*tid+1). Block covers 512 h (one half).
// Writes RAW partial sums h1/h3 (no silu) to per-half buffers.

__device__ __forceinline__ void mlp1_issue(
    const float* __restrict__ wg, const float* __restrict__ wu,
    float (*ws)[2][4][II], int st, int hq, int wrp, int lane)
{
#pragma unroll
    for (int j = 0; j < 4; j++) {
        int s = lane + 32 * j;
        int m = s >> 6, h = (s >> 4) & 3, q = s & 15;
        const float* src = (m ? wu : wg) + (hq * 4 + h) * II + wrp * 64 + q * 4;
        cp16(smem_u32(&ws[st][m][h][wrp * 64 + q * 4]), src);
    }
    cp_commit();
}

template <int TTP>   // token pairs: 4 or 8
__device__ __forceinline__ void mlp1_tile(
    const float* __restrict__ x, int hbase,
    const float* __restrict__ wg, const float* __restrict__ wu,  // pre-offset by hbase*II
    const int* s_toks, int nt,
    float* __restrict__ p1_base, float* __restrict__ p3_base,
    float (*ws)[2][4][II], u64 (*xs)[256])
{
    const int tid = threadIdx.x;
    const int lane = tid & 31, wrp = tid >> 5;
    cp_wait<0>();
    __syncwarp();
    u64 ag0[TTP], ag1[TTP], au0[TTP], au1[TTP];
#pragma unroll
    for (int p = 0; p < TTP; p++) { ag0[p] = 0; ag1[p] = 0; au0[p] = 0; au1[p] = 0; }

    mlp1_issue(wg, wu, ws, 0, 0, wrp, lane);
    mlp1_issue(wg, wu, ws, 1, 1, wrp, lane);
    mlp1_issue(wg, wu, ws, 2, 2, wrp, lane);

#pragma unroll 1
    for (int s = 0; s < 128; s++) {
        if ((s & 63) == 0) {
            int h0 = hbase + ((s >> 6) << 8);
            __syncthreads();
            for (int idx = tid; idx < TTP * 2 * 64; idx += 128) {
                int t2 = idx >> 6, hq = idx & 63;
                float4 v = make_float4(0.f, 0.f, 0.f, 0.f);
                if (t2 < nt) v = *(const float4*)(x + s_toks[t2] * HH + h0 + hq * 4);
                float* bp = (float*)&xs[t2 >> 1][hq * 4];
                int q = t2 & 1;
                bp[0 + q] = v.x; bp[2 + q] = v.y; bp[4 + q] = v.z; bp[6 + q] = v.w;
            }
            __syncthreads();
        }
        if (s + 3 < 128) mlp1_issue(wg, wu, ws, (s + 3) & 3, s + 3, wrp, lane);
        else cp_commit();
        cp_wait<3>();
        __syncwarp();
        const int st = s & 3;
        const int hl = (s & 63) * 4;
#pragma unroll
        for (int hh = 0; hh < 2; hh++) {
            float2 a0 = *(const float2*)&ws[st][0][2 * hh][2 * tid];
            float2 a1 = *(const float2*)&ws[st][0][2 * hh + 1][2 * tid];
            float2 b0 = *(const float2*)&ws[st][1][2 * hh][2 * tid];
            float2 b1 = *(const float2*)&ws[st][1][2 * hh + 1][2 * tid];
            u64 wgc0h0 = pack2(a0.x, a0.x), wgc1h0 = pack2(a0.y, a0.y);
            u64 wgc0h1 = pack2(a1.x, a1.x), wgc1h1 = pack2(a1.y, a1.y);
            u64 wuc0h0 = pack2(b0.x, b0.x), wuc1h0 = pack2(b0.y, b0.y);
            u64 wuc0h1 = pack2(b1.x, b1.x), wuc1h1 = pack2(b1.y, b1.y);
#pragma unroll
            for (int p = 0; p < TTP; p++) {
                ulonglong2 xv = *(const ulonglong2*)&xs[p][hl + 2 * hh];
                ag0[p] = fma2(xv.x, wgc0h0, ag0[p]);
                ag1[p] = fma2(xv.x, wgc1h0, ag1[p]);
                au0[p] = fma2(xv.x, wuc0h0, au0[p]);
                au1[p] = fma2(xv.x, wuc1h0, au1[p]);
                ag0[p] = fma2(xv.y, wgc0h1, ag0[p]);
                ag1[p] = fma2(xv.y, wgc1h1, ag1[p]);
                au0[p] = fma2(xv.y, wuc0h1, au0[p]);
                au1[p] = fma2(xv.y, wuc1h1, au1[p]);
            }
        }
    }
#pragma unroll
    for (int p = 0; p < TTP; p++) {
        float2 g0 = unpack2(ag0[p]);   // (t0,c0),(t1,c0)
        float2 g1 = unpack2(ag1[p]);   // (t0,c1),(t1,c1)
        float2 u0 = unpack2(au0[p]);
        float2 u1 = unpack2(au1[p]);
        int t0 = 2 * p, t1 = 2 * p + 1;
        if (t0 < nt) {
            *(float2*)(p1_base + (size_t)t0 * II + 2 * tid) = make_float2(g0.x, g1.x);
            *(float2*)(p3_base + (size_t)t0 * II + 2 * tid) = make_float2(u0.x, u1.x);
        }
        if (t1 < nt) {
            *(float2*)(p1_base + (size_t)t1 * II + 2 * tid) = make_float2(g0.y, g1.y);
            *(float2*)(p3_base + (size_t)t1 * II + 2 * tid) = make_float2(u0.y, u1.y);
        }
    }
}

// grid.x = 2*(EE + 16): bit0 = h-half, rest = expert / shared tile
__global__ void __launch_bounds__(128, 4) k_mlp1(
    const float* __restrict__ x,
    const float* __restrict__ wgate, const float* __restrict__ wup,
    const float* __restrict__ swg, const float* __restrict__ swu)
{
    __shared__ float ws[4][2][4][II];   // 32 KB weight ring
    __shared__ u64 xs[8][256];          // 16 KB token-paired x chunk
    __shared__ int s_toks[16];
    int b = blockIdx.x;
    int hf = b & 1;
    int eb = b >> 1;
    int hbase = hf * 512;
    if (eb < EE) {
        int cnt = g_cnt[eb];
        if (cnt == 0) return;
        int base = g_base[eb];
        const float* wg = wgate + (size_t)eb * HH * II + (size_t)hbase * II;
        const float* wu = wup   + (size_t)eb * HH * II + (size_t)hbase * II;
        for (int off = 0; off < cnt; off += 16) {
            int nt = min(cnt - off, 16);
            if (threadIdx.x < nt)
                s_toks[threadIdx.x] = g_pair_tok[base + off + threadIdx.x];
            float* p1 = g_p1[hf] + (size_t)(base + off) * II;
            float* p3 = g_p3[hf] + (size_t)(base + off) * II;
            if (nt <= 8) mlp1_tile<4>(x, hbase, wg, wu, s_toks, nt, p1, p3, ws, xs);
            else         mlp1_tile<8>(x, hbase, wg, wu, s_toks, nt, p1, p3, ws, xs);
        }
    } else {
        int j = eb - EE;
        if (threadIdx.x < 16) s_toks[threadIdx.x] = j * 16 + threadIdx.x;
        mlp1_tile<8>(x, hbase, swg + (size_t)hbase * II, swu + (size_t)hbase * II,
                     s_toks, 16,
                     g_sp1[hf] + (size_t)j * 16 * II,
                     g_sp3[hf] + (size_t)j * 16 * II, ws, xs);
    }
}

// ================= down: token-pair x col-pair blocking; act built from partials =================

__device__ __forceinline__ void down_issue(
    const float* __restrict__ wdc, float (*ws2)[4][256],
    int st, int iq, int wrp, int lane)
{
#pragma unroll
    for (int j = 0; j < 2; j++) {
        int s = lane + 32 * j;
        int i = s >> 4, q = s & 15;
        cp16(smem_u32(&ws2[st][i][wrp * 64 + q * 4]),
             wdc + (size_t)(iq * 4 + i) * HH + wrp * 64 + q * 4);
    }
    cp_commit();
}

template <int TTP>
__device__ __forceinline__ void down_tile(
    const float* __restrict__ wdc,            // wd + hc*256
    const int* s_toks, const float* s_w, int nt,
    float* __restrict__ outc,                 // out + hc*256
    u64 (*as4)[256], float (*ws2)[4][256])
{
    const int tid = threadIdx.x;
    const int lane = tid & 31, wrp = tid >> 5;
    cp_wait<0>();
    __syncwarp();
    u64 acc0[TTP], acc1[TTP];
#pragma unroll
    for (int p = 0; p < TTP; p++) { acc0[p] = 0; acc1[p] = 0; }

    down_issue(wdc, ws2, 0, 0, wrp, lane);
    down_issue(wdc, ws2, 1, 1, wrp, lane);
    down_issue(wdc, ws2, 2, 2, wrp, lane);

#pragma unroll 1
    for (int s = 0; s < 64; s++) {
        if (s + 3 < 64) down_issue(wdc, ws2, (s + 3) & 3, s + 3, wrp, lane);
        else cp_commit();
        cp_wait<3>();
        __syncwarp();
        const int st = s & 3;
        const int il = s * 4;
#pragma unroll
        for (int ii = 0; ii < 2; ii++) {
            float2 a0 = *(const float2*)&ws2[st][2 * ii][2 * tid];
            float2 a1 = *(const float2*)&ws2[st][2 * ii + 1][2 * tid];
            u64 wc0i0 = pack2(a0.x, a0.x), wc1i0 = pack2(a0.y, a0.y);
            u64 wc0i1 = pack2(a1.x, a1.x), wc1i1 = pack2(a1.y, a1.y);
#pragma unroll
            for (int p = 0; p < TTP; p++) {
                ulonglong2 av = *(const ulonglong2*)&as4[p][il + 2 * ii];
                acc0[p] = fma2(av.x, wc0i0, acc0[p]);
                acc1[p] = fma2(av.x, wc1i0, acc1[p]);
                acc0[p] = fma2(av.y, wc0i1, acc0[p]);
                acc1[p] = fma2(av.y, wc1i1, acc1[p]);
            }
        }
    }
#pragma unroll
    for (int p = 0; p < TTP; p++) {
        float2 r0 = unpack2(acc0[p]);   // (t0,c0),(t1,c0)
        float2 r1 = unpack2(acc1[p]);   // (t0,c1),(t1,c1)
        int t0 = 2 * p, t1 = 2 * p + 1;
        if (t0 < nt) {
            float* o = outc + (size_t)s_toks[t0] * HH + 2 * tid;
            atomicAdd(o,     s_w[t0] * r0.x);
            atomicAdd(o + 1, s_w[t0] * r1.x);
        }
        if (t1 < nt) {
            float* o = outc + (size_t)s_toks[t1] * HH + 2 * tid;
            atomicAdd(o,     s_w[t1] * r0.y);
            atomicAdd(o + 1, s_w[t1] * r1.y);
        }
    }
}

__global__ void __launch_bounds__(128, 4) k_down(
    const float* __restrict__ wdown, const float* __restrict__ swd,
    float* __restrict__ out)
{
    __shared__ float ws2[4][4][256];    // 16 KB weight ring
    __shared__ u64 as4[8][256];         // 16 KB token-paired act
    __shared__ int s_toks[16];
    __shared__ float s_w[16];
    int b = blockIdx.x;
    int hc = blockIdx.y;
    if (b < EE) {
        int cnt = g_cnt[b];
        if (cnt == 0) return;
        int base = g_base[b];
        const float* wdc = wdown + (size_t)b * II * HH + hc * 256;
        for (int off = 0; off < cnt; off += 16) {
            int nt = min(cnt - off, 16);
            __syncthreads();
            if (threadIdx.x < nt) {
                s_toks[threadIdx.x] = g_pair_tok[base + off + threadIdx.x];
                s_w[threadIdx.x]    = g_pair_w[base + off + threadIdx.x];
            }
#pragma unroll
            for (int p = 0; p < 8; p++) {
                int t0 = 2 * p, t1 = 2 * p + 1;
                for (int i = threadIdx.x; i < II; i += 128) {
                    float v0 = 0.f, v1 = 0.f;
                    if (t0 < nt) {
                        size_t ix = (size_t)(base + off + t0) * II + i;
                        v0 = silu_mul(g_p1[0][ix] + g_p1[1][ix],
                                      g_p3[0][ix] + g_p3[1][ix]);
                    }
                    if (t1 < nt) {
                        size_t ix = (size_t)(base + off + t1) * II + i;
                        v1 = silu_mul(g_p1[0][ix] + g_p1[1][ix],
                                      g_p3[0][ix] + g_p3[1][ix]);
                    }
                    as4[p][i] = pack2(v0, v1);
                }
            }
            __syncthreads();
            if (nt <= 8) down_tile<4>(wdc, s_toks, s_w, nt, out + hc * 256, as4, ws2);
            else         down_tile<8>(wdc, s_toks, s_w, nt, out + hc * 256, as4, ws2);
        }
    } else {
        int j = b - EE;
        if (threadIdx.x < 16) {
            s_toks[threadIdx.x] = j * 16 + threadIdx.x;
            s_w[threadIdx.x] = 1.0f;
        }
#pragma unroll
        for (int p = 0; p < 8; p++) {
            for (int i = threadIdx.x; i < II; i += 128) {
                size_t ix0 = (size_t)(j * 16 + 2 * p)     * II + i;
                size_t ix1 = (size_t)(j * 16 + 2 * p + 1) * II + i;
                float v0 = silu_mul(g_sp1[0][ix0] + g_sp1[1][ix0],
                                    g_sp3[0][ix0] + g_sp3[1][ix0]);
                float v1 = silu_mul(g_sp1[0][ix1] + g_sp1[1][ix1],
                                    g_sp3[0][ix1] + g_sp3[1][ix1]);
                as4[p][i] = pack2(v0, v1);
            }
        }
        __syncthreads();
        down_tile<8>(swd + hc * 256, s_toks, s_w, 16, out + hc * 256, as4, ws2);
    }
}

// ---------------- launch ----------------
extern "C" void kernel_launch(void* const* d_in, const int* in_sizes, int n_in,
                              void* d_out, int out_size)
{
    const float* x       = (const float*)d_in[0];  // [1,1,T,H]
    const float* gate_w  = (const float*)d_in[1];  // [E,H]
    const float* e_bias  = (const float*)d_in[2];  // [E]
    const float* w_gate  = (const float*)d_in[3];  // [E,H,I]
    const float* w_up    = (const float*)d_in[4];  // [E,H,I]
    const float* w_down  = (const float*)d_in[5];  // [E,I,H]
    const float* sw_gate = (const float*)d_in[6];  // [H,I]
    const float* sw_up   = (const float*)d_in[7];  // [H,I]
    const float* sw_down = (const float*)d_in[8];  // [I,H]
    float* out = (float*)d_out;                    // [1,1,T,H] fp32

    k_zero<<<(TT_T * HH + 255) / 256, 256>>>(out, TT_T * HH);
    k_gate<<<256, 256>>>(x, gate_w);
    k_route<<<1, 256>>>(e_bias);
    k_mlp1<<<(EE + 16) * 2, 128>>>(x, w_gate, w_up, sw_gate, sw_up);
    k_down<<<dim3(EE + 16, 4), 128>>>(w_down, sw_down, out);
}

// round 9
// speedup vs baseline: 1.5465x; 1.5465x over previous
#include <cuda_runtime.h>
#include <cstdint>
#include <cstddef>

#define TT_T 256      // tokens
#define HH 1024       // hidden
#define EE 256        // experts
#define II 256        // intermediate
#define NPAIR 2048    // T * top_k
#define MAXITEMS 384  // max routed token tiles (sum ceil(cnt/16) <= 256 + 128)

typedef unsigned long long u64;

// ---------------- scratch (device globals; no allocations allowed) ----------------
__device__ float g_scores[TT_T * EE];
__device__ int   g_cnt[EE];
__device__ int   g_base[EE];
__device__ int   g_pair_tok[NPAIR];
__device__ float g_pair_w[NPAIR];
__device__ int   g_items[MAXITEMS];          // (e << 16) | off
__device__ int   g_nitems;
// partial sums (per h-half) for routed experts and shared expert
__device__ float g_p1[2][NPAIR * II];
__device__ float g_p3[2][NPAIR * II];
__device__ float g_sp1[2][TT_T * II];
__device__ float g_sp3[2][TT_T * II];

// ---------------- f32x2 / async helpers ----------------
__device__ __forceinline__ u64 fma2(u64 a, u64 b, u64 c) {
    u64 d;
    asm("fma.rn.f32x2 %0, %1, %2, %3;" : "=l"(d) : "l"(a), "l"(b), "l"(c));
    return d;
}
__device__ __forceinline__ u64 pack2(float x, float y) {
    u64 r;
    asm("mov.b64 %0, {%1, %2};" : "=l"(r) : "f"(x), "f"(y));
    return r;
}
__device__ __forceinline__ float2 unpack2(u64 v) {
    float2 r;
    asm("mov.b64 {%0, %1}, %2;" : "=f"(r.x), "=f"(r.y) : "l"(v));
    return r;
}
__device__ __forceinline__ unsigned smem_u32(const void* p) {
    return (unsigned)__cvta_generic_to_shared(p);
}
__device__ __forceinline__ void cp16(unsigned dst, const void* src) {
    asm volatile("cp.async.cg.shared.global [%0], [%1], 16;\n" :: "r"(dst), "l"(src));
}
__device__ __forceinline__ void cp_commit() { asm volatile("cp.async.commit_group;\n"); }
template <int N>
__device__ __forceinline__ void cp_wait() { asm volatile("cp.async.wait_group %0;\n" :: "n"(N)); }
__device__ __forceinline__ float silu_mul(float g, float u) {
    return g / (1.f + __expf(-g)) * u;
}

// ---------------- kernel: zero output ----------------
__global__ void k_zero(float* __restrict__ out, int n) {
    int i = blockIdx.x * blockDim.x + threadIdx.x;
    if (i < n) out[i] = 0.f;
}

// ---------------- kernel: gate scores = sigmoid(x @ gate_w^T) ----------------
__global__ void k_gate(const float* __restrict__ x, const float* __restrict__ gw) {
    __shared__ float gws[8 * HH];
    int eg = blockIdx.x & 31;
    int tg = blockIdx.x >> 5;
    int tid = threadIdx.x;
    for (int idx = tid; idx < 8 * HH; idx += 256)
        gws[idx] = gw[eg * 8 * HH + idx];
    __syncthreads();
    int warp = tid >> 5, lane = tid & 31;
    for (int tt = warp; tt < 32; tt += 8) {
        int t = tg * 32 + tt;
        float acc[8];
#pragma unroll
        for (int e = 0; e < 8; e++) acc[e] = 0.f;
        for (int h = lane; h < HH; h += 32) {
            float xv = x[t * HH + h];
#pragma unroll
            for (int e = 0; e < 8; e++) acc[e] += xv * gws[e * HH + h];
        }
#pragma unroll
        for (int e = 0; e < 8; e++) {
            float v = acc[e];
#pragma unroll
            for (int s = 16; s > 0; s >>= 1) v += __shfl_xor_sync(0xffffffffu, v, s);
            if (lane == e)
                g_scores[t * EE + eg * 8 + e] = 1.f / (1.f + __expf(-v));
        }
    }
}

// ---------------- kernel: routing (1 block, thread = token) ----------------
__global__ void k_route(const float* __restrict__ e_bias) {
    int t = threadIdx.x;
    __shared__ float s_bias[EE];
    __shared__ int s_cnt[EE];
    __shared__ int s_ofs[EE];
    s_bias[t] = e_bias[t];
    s_cnt[t] = 0;
    __syncthreads();
    const float* srow = g_scores + t * EE;

    float gsum[8];
#pragma unroll
    for (int g = 0; g < 8; g++) {
        float m1 = -1e30f, m2 = -1e30f;
        for (int j = 0; j < 32; j++) {
            float v = srow[g * 32 + j] + s_bias[g * 32 + j];
            if (v > m1) { m2 = m1; m1 = v; }
            else if (v > m2) { m2 = v; }
        }
        gsum[g] = m1 + m2;
    }
    unsigned gmask = 0;
    for (int it = 0; it < 4; it++) {
        float best = -1e30f; int bi = 0;
#pragma unroll
        for (int g = 0; g < 8; g++)
            if (!((gmask >> g) & 1u) && gsum[g] > best) { best = gsum[g]; bi = g; }
        gmask |= 1u << bi;
    }
    float bv[8]; int bidx[8];
#pragma unroll
    for (int k = 0; k < 8; k++) { bv[k] = -1e30f; bidx[k] = -1; }
    for (int g = 0; g < 8; g++) {
        if (!((gmask >> g) & 1u)) continue;
        for (int j = 0; j < 32; j++) {
            int e = g * 32 + j;
            float v = srow[e] + s_bias[e];
            if (v > bv[7]) {
#pragma unroll
                for (int k = 7; k > 0; k--) {
                    bool sh = v > bv[k - 1];
                    bool ins = (v > bv[k]) && !sh;
                    float nv = sh ? bv[k - 1] : (ins ? v : bv[k]);
                    int   ni = sh ? bidx[k - 1] : (ins ? e : bidx[k]);
                    bv[k] = nv; bidx[k] = ni;
                }
                if (v > bv[0]) { bv[0] = v; bidx[0] = e; }
            }
        }
    }
    float w[8]; float wsum = 0.f;
#pragma unroll
    for (int k = 0; k < 8; k++) { w[k] = srow[bidx[k]]; wsum += w[k]; }
    float scl = 2.5f / (wsum + 1e-20f);
#pragma unroll
    for (int k = 0; k < 8; k++) {
        w[k] *= scl;
        atomicAdd(&s_cnt[bidx[k]], 1);
    }
    __syncthreads();
    int base = 0;
    for (int e = 0; e < t; e++) base += s_cnt[e];
    s_ofs[t] = base;
    g_base[t] = base;
    g_cnt[t] = s_cnt[t];
    __syncthreads();
    // build uniform tile work-item list (thread 0, deterministic)
    if (t == 0) {
        int n = 0;
        for (int e = 0; e < EE; e++) {
            int c = s_cnt[e];
            for (int off = 0; off < c; off += 16)
                g_items[n++] = (e << 16) | off;
        }
        g_nitems = n;
    }
#pragma unroll
    for (int k = 0; k < 8; k++) {
        int slot = atomicAdd(&s_ofs[bidx[k]], 1);
        g_pair_tok[slot] = t;
        g_pair_w[slot] = w[k];
    }
}

// ================= mlp1: token-pair x col-pair blocking, h-half split =================
// 128 threads; thread owns cols (2*tid, 2*tid+1). Block covers 512 h (one half), ONE tile.
// Writes RAW partial sums h1/h3 (no silu) to per-half buffers.

__device__ __forceinline__ void mlp1_issue(
    const float* __restrict__ wg, const float* __restrict__ wu,
    float (*ws)[2][4][II], int st, int hq, int wrp, int lane)
{
#pragma unroll
    for (int j = 0; j < 4; j++) {
        int s = lane + 32 * j;
        int m = s >> 6, h = (s >> 4) & 3, q = s & 15;
        const float* src = (m ? wu : wg) + (hq * 4 + h) * II + wrp * 64 + q * 4;
        cp16(smem_u32(&ws[st][m][h][wrp * 64 + q * 4]), src);
    }
    cp_commit();
}

template <int TTP>   // token pairs: 4 or 8
__device__ __forceinline__ void mlp1_tile(
    const float* __restrict__ x, int hbase,
    const float* __restrict__ wg, const float* __restrict__ wu,  // pre-offset by hbase*II
    const int* s_toks, int nt,
    float* __restrict__ p1_base, float* __restrict__ p3_base,
    float (*ws)[2][4][II], u64 (*xs)[256])
{
    const int tid = threadIdx.x;
    const int lane = tid & 31, wrp = tid >> 5;
    u64 ag0[TTP], ag1[TTP], au0[TTP], au1[TTP];
#pragma unroll
    for (int p = 0; p < TTP; p++) { ag0[p] = 0; ag1[p] = 0; au0[p] = 0; au1[p] = 0; }

    mlp1_issue(wg, wu, ws, 0, 0, wrp, lane);
    mlp1_issue(wg, wu, ws, 1, 1, wrp, lane);
    mlp1_issue(wg, wu, ws, 2, 2, wrp, lane);

#pragma unroll 1
    for (int s = 0; s < 128; s++) {
        if ((s & 63) == 0) {
            int h0 = hbase + ((s >> 6) << 8);
            __syncthreads();
            for (int idx = tid; idx < TTP * 2 * 64; idx += 128) {
                int t2 = idx >> 6, hq = idx & 63;
                float4 v = make_float4(0.f, 0.f, 0.f, 0.f);
                if (t2 < nt) v = *(const float4*)(x + s_toks[t2] * HH + h0 + hq * 4);
                float* bp = (float*)&xs[t2 >> 1][hq * 4];
                int q = t2 & 1;
                bp[0 + q] = v.x; bp[2 + q] = v.y; bp[4 + q] = v.z; bp[6 + q] = v.w;
            }
            __syncthreads();
        }
        if (s + 3 < 128) mlp1_issue(wg, wu, ws, (s + 3) & 3, s + 3, wrp, lane);
        else cp_commit();
        cp_wait<3>();
        __syncwarp();
        const int st = s & 3;
        const int hl = (s & 63) * 4;
#pragma unroll
        for (int hh = 0; hh < 2; hh++) {
            float2 a0 = *(const float2*)&ws[st][0][2 * hh][2 * tid];
            float2 a1 = *(const float2*)&ws[st][0][2 * hh + 1][2 * tid];
            float2 b0 = *(const float2*)&ws[st][1][2 * hh][2 * tid];
            float2 b1 = *(const float2*)&ws[st][1][2 * hh + 1][2 * tid];
            u64 wgc0h0 = pack2(a0.x, a0.x), wgc1h0 = pack2(a0.y, a0.y);
            u64 wgc0h1 = pack2(a1.x, a1.x), wgc1h1 = pack2(a1.y, a1.y);
            u64 wuc0h0 = pack2(b0.x, b0.x), wuc1h0 = pack2(b0.y, b0.y);
            u64 wuc0h1 = pack2(b1.x, b1.x), wuc1h1 = pack2(b1.y, b1.y);
#pragma unroll
            for (int p = 0; p < TTP; p++) {
                ulonglong2 xv = *(const ulonglong2*)&xs[p][hl + 2 * hh];
                ag0[p] = fma2(xv.x, wgc0h0, ag0[p]);
                ag1[p] = fma2(xv.x, wgc1h0, ag1[p]);
                au0[p] = fma2(xv.x, wuc0h0, au0[p]);
                au1[p] = fma2(xv.x, wuc1h0, au1[p]);
                ag0[p] = fma2(xv.y, wgc0h1, ag0[p]);
                ag1[p] = fma2(xv.y, wgc1h1, ag1[p]);
                au0[p] = fma2(xv.y, wuc0h1, au0[p]);
                au1[p] = fma2(xv.y, wuc1h1, au1[p]);
            }
        }
    }
    cp_wait<0>();
#pragma unroll
    for (int p = 0; p < TTP; p++) {
        float2 g0 = unpack2(ag0[p]);   // (t0,c0),(t1,c0)
        float2 g1 = unpack2(ag1[p]);   // (t0,c1),(t1,c1)
        float2 u0 = unpack2(au0[p]);
        float2 u1 = unpack2(au1[p]);
        int t0 = 2 * p, t1 = 2 * p + 1;
        if (t0 < nt) {
            *(float2*)(p1_base + (size_t)t0 * II + 2 * tid) = make_float2(g0.x, g1.x);
            *(float2*)(p3_base + (size_t)t0 * II + 2 * tid) = make_float2(u0.x, u1.x);
        }
        if (t1 < nt) {
            *(float2*)(p1_base + (size_t)t1 * II + 2 * tid) = make_float2(g0.y, g1.y);
            *(float2*)(p3_base + (size_t)t1 * II + 2 * tid) = make_float2(u0.y, u1.y);
        }
    }
}

// grid.x = 800: [0,768) routed: item = g_items[b>>1], h-half = b&1;
//               [768,800): shared tiles: tile = (b-768)>>1, h-half = (b-768)&1
__global__ void __launch_bounds__(128, 4) k_mlp1(
    const float* __restrict__ x,
    const float* __restrict__ wgate, const float* __restrict__ wup,
    const float* __restrict__ swg, const float* __restrict__ swu)
{
    __shared__ float ws[4][2][4][II];   // 32 KB weight ring
    __shared__ u64 xs[8][256];          // 16 KB token-paired x chunk
    __shared__ int s_toks[16];
    int b = blockIdx.x;
    if (b < 768) {
        if ((b >> 1) >= g_nitems) return;
        int item = g_items[b >> 1];
        int hf = b & 1;
        int e = item >> 16, off = item & 0xffff;
        int hbase = hf * 512;
        int base = g_base[e];
        int nt = min(g_cnt[e] - off, 16);
        if (threadIdx.x < nt)
            s_toks[threadIdx.x] = g_pair_tok[base + off + threadIdx.x];
        const float* wg = wgate + (size_t)e * HH * II + (size_t)hbase * II;
        const float* wu = wup   + (size_t)e * HH * II + (size_t)hbase * II;
        float* p1 = g_p1[hf] + (size_t)(base + off) * II;
        float* p3 = g_p3[hf] + (size_t)(base + off) * II;
        if (nt <= 8) mlp1_tile<4>(x, hbase, wg, wu, s_toks, nt, p1, p3, ws, xs);
        else         mlp1_tile<8>(x, hbase, wg, wu, s_toks, nt, p1, p3, ws, xs);
    } else {
        int j = b - 768;
        int tile = j >> 1, hf = j & 1;
        int hbase = hf * 512;
        if (threadIdx.x < 16) s_toks[threadIdx.x] = tile * 16 + threadIdx.x;
        mlp1_tile<8>(x, hbase, swg + (size_t)hbase * II, swu + (size_t)hbase * II,
                     s_toks, 16,
                     g_sp1[hf] + (size_t)tile * 16 * II,
                     g_sp3[hf] + (size_t)tile * 16 * II, ws, xs);
    }
}

// ================= down: token-pair x col-pair blocking; act built from partials =================

__device__ __forceinline__ void down_issue(
    const float* __restrict__ wdc, float (*ws2)[4][256],
    int st, int iq, int wrp, int lane)
{
#pragma unroll
    for (int j = 0; j < 2; j++) {
        int s = lane + 32 * j;
        int i = s >> 4, q = s & 15;
        cp16(smem_u32(&ws2[st][i][wrp * 64 + q * 4]),
             wdc + (size_t)(iq * 4 + i) * HH + wrp * 64 + q * 4);
    }
    cp_commit();
}

template <int TTP>
__device__ __forceinline__ void down_tile(
    const float* __restrict__ wdc,            // wd + hc*256
    const int* s_toks, const float* s_w, int nt,
    float* __restrict__ outc,                 // out + hc*256
    u64 (*as4)[256], float (*ws2)[4][256])
{
    const int tid = threadIdx.x;
    const int lane = tid & 31, wrp = tid >> 5;
    u64 acc0[TTP], acc1[TTP];
#pragma unroll
    for (int p = 0; p < TTP; p++) { acc0[p] = 0; acc1[p] = 0; }

    down_issue(wdc, ws2, 0, 0, wrp, lane);
    down_issue(wdc, ws2, 1, 1, wrp, lane);
    down_issue(wdc, ws2, 2, 2, wrp, lane);

#pragma unroll 1
    for (int s = 0; s < 64; s++) {
        if (s + 3 < 64) down_issue(wdc, ws2, (s + 3) & 3, s + 3, wrp, lane);
        else cp_commit();
        cp_wait<3>();
        __syncwarp();
        const int st = s & 3;
        const int il = s * 4;
#pragma unroll
        for (int ii = 0; ii < 2; ii++) {
            float2 a0 = *(const float2*)&ws2[st][2 * ii][2 * tid];
            float2 a1 = *(const float2*)&ws2[st][2 * ii + 1][2 * tid];
            u64 wc0i0 = pack2(a0.x, a0.x), wc1i0 = pack2(a0.y, a0.y);
            u64 wc0i1 = pack2(a1.x, a1.x), wc1i1 = pack2(a1.y, a1.y);
#pragma unroll
            for (int p = 0; p < TTP; p++) {
                ulonglong2 av = *(const ulonglong2*)&as4[p][il + 2 * ii];
                acc0[p] = fma2(av.x, wc0i0, acc0[p]);
                acc1[p] = fma2(av.x, wc1i0, acc1[p]);
                acc0[p] = fma2(av.y, wc0i1, acc0[p]);
                acc1[p] = fma2(av.y, wc1i1, acc1[p]);
            }
        }
    }
    cp_wait<0>();
#pragma unroll
    for (int p = 0; p < TTP; p++) {
        float2 r0 = unpack2(acc0[p]);   // (t0,c0),(t1,c0)
        float2 r1 = unpack2(acc1[p]);   // (t0,c1),(t1,c1)
        int t0 = 2 * p, t1 = 2 * p + 1;
        if (t0 < nt) {
            float* o = outc + (size_t)s_toks[t0] * HH + 2 * tid;
            atomicAdd(o,     s_w[t0] * r0.x);
            atomicAdd(o + 1, s_w[t0] * r1.x);
        }
        if (t1 < nt) {
            float* o = outc + (size_t)s_toks[t1] * HH + 2 * tid;
            atomicAdd(o,     s_w[t1] * r0.y);
            atomicAdd(o + 1, s_w[t1] * r1.y);
        }
    }
}

// grid: (400, 4): x<384 routed item; x in [384,400) shared tile; y = h-chunk
__global__ void __launch_bounds__(128, 4) k_down(
    const float* __restrict__ wdown, const float* __restrict__ swd,
    float* __restrict__ out)
{
    __shared__ float ws2[4][4][256];    // 16 KB weight ring
    __shared__ u64 as4[8][256];         // 16 KB token-paired act
    __shared__ int s_toks[16];
    __shared__ float s_w[16];
    int b = blockIdx.x;
    int hc = blockIdx.y;
    if (b < MAXITEMS) {
        if (b >= g_nitems) return;
        int item = g_items[b];
        int e = item >> 16, off = item & 0xffff;
        int base = g_base[e];
        int nt = min(g_cnt[e] - off, 16);
        const float* wdc = wdown + (size_t)e * II * HH + hc * 256;
        if (threadIdx.x < nt) {
            s_toks[threadIdx.x] = g_pair_tok[base + off + threadIdx.x];
            s_w[threadIdx.x]    = g_pair_w[base + off + threadIdx.x];
        }
#pragma unroll
        for (int p = 0; p < 8; p++) {
            int t0 = 2 * p, t1 = 2 * p + 1;
            for (int i = threadIdx.x; i < II; i += 128) {
                float v0 = 0.f, v1 = 0.f;
                if (t0 < nt) {
                    size_t ix = (size_t)(base + off + t0) * II + i;
                    v0 = silu_mul(g_p1[0][ix] + g_p1[1][ix],
                                  g_p3[0][ix] + g_p3[1][ix]);
                }
                if (t1 < nt) {
                    size_t ix = (size_t)(base + off + t1) * II + i;
                    v1 = silu_mul(g_p1[0][ix] + g_p1[1][ix],
                                  g_p3[0][ix] + g_p3[1][ix]);
                }
                as4[p][i] = pack2(v0, v1);
            }
        }
        __syncthreads();
        if (nt <= 8) down_tile<4>(wdc, s_toks, s_w, nt, out + hc * 256, as4, ws2);
        else         down_tile<8>(wdc, s_toks, s_w, nt, out + hc * 256, as4, ws2);
    } else {
        int j = b - MAXITEMS;           // shared tile 0..15
        if (threadIdx.x < 16) {
            s_toks[threadIdx.x] = j * 16 + threadIdx.x;
            s_w[threadIdx.x] = 1.0f;
        }
#pragma unroll
        for (int p = 0; p < 8; p++) {
            for (int i = threadIdx.x; i < II; i += 128) {
                size_t ix0 = (size_t)(j * 16 + 2 * p)     * II + i;
                size_t ix1 = (size_t)(j * 16 + 2 * p + 1) * II + i;
                float v0 = silu_mul(g_sp1[0][ix0] + g_sp1[1][ix0],
                                    g_sp3[0][ix0] + g_sp3[1][ix0]);
                float v1 = silu_mul(g_sp1[0][ix1] + g_sp1[1][ix1],
                                    g_sp3[0][ix1] + g_sp3[1][ix1]);
                as4[p][i] = pack2(v0, v1);
            }
        }
        __syncthreads();
        down_tile<8>(swd + hc * 256, s_toks, s_w, 16, out + hc * 256, as4, ws2);
    }
}

// ---------------- launch ----------------
extern "C" void kernel_launch(void* const* d_in, const int* in_sizes, int n_in,
                              void* d_out, int out_size)
{
    const float* x       = (const float*)d_in[0];  // [1,1,T,H]
    const float* gate_w  = (const float*)d_in[1];  // [E,H]
    const float* e_bias  = (const float*)d_in[2];  // [E]
    const float* w_gate  = (const float*)d_in[3];  // [E,H,I]
    const float* w_up    = (const float*)d_in[4];  // [E,H,I]
    const float* w_down  = (const float*)d_in[5];  // [E,I,H]
    const float* sw_gate = (const float*)d_in[6];  // [H,I]
    const float* sw_up   = (const float*)d_in[7];  // [H,I]
    const float* sw_down = (const float*)d_in[8];  // [I,H]
    float* out = (float*)d_out;                    // [1,1,T,H] fp32

    k_zero<<<(TT_T * HH + 255) / 256, 256>>>(out, TT_T * HH);
    k_gate<<<256, 256>>>(x, gate_w);
    k_route<<<1, 256>>>(e_bias);
    k_mlp1<<<768 + 32, 128>>>(x, w_gate, w_up, sw_gate, sw_up);
    k_down<<<dim3(MAXITEMS + 16, 4), 128>>>(w_down, sw_down, out);
}